// round 15
// baseline (speedup 1.0000x reference)
#include <cuda_runtime.h>
#include <cuda_fp16.h>
#include <cstdint>
#include <math.h>

#define B_  4
#define S_  2048
#define E_  768
#define H_  3
#define D_  256

// fp16 GEMM params
#define BKH 64
#define PAH 72      // halves; ldmatrix group banks all distinct
#define PBH 136     // halves; ldmatrix.trans group banks all distinct
#define ASTGH (128 * PAH)
#define BSTGH_T (BKH * PBH)
#define BSTGH_N (128 * PAH)

#define NROWS (B_ * H_ * S_)        // 24576

// Scratch (device globals — no allocation allowed)
__device__ __half g_Q[(size_t)B_ * H_ * S_ * D_];
__device__ __half g_K[(size_t)B_ * H_ * S_ * D_];
__device__ __half g_V[(size_t)B_ * H_ * S_ * D_];
__device__ __half g_P[(size_t)B_ * H_ * S_ * S_];   // UNNORMALIZED exp scores (half)
__device__ float  g_psum[(size_t)NROWS * 64];       // per-(row, stripe) partial sums
__device__ float  g_rsum[NROWS];                    // 1 / row sum
__device__ __half g_C[(size_t)B_ * S_ * E_];        // concat heads (half)

// ---------------------------------------------------------------------------
__device__ __forceinline__ uint32_t sptr(const void* p) {
    return (uint32_t)__cvta_generic_to_shared(p);
}
#define CP16(dst, src) \
    asm volatile("cp.async.cg.shared.global [%0], [%1], 16;" :: "r"(dst), "l"(src))
#define CP_COMMIT() asm volatile("cp.async.commit_group;")
#define LDSM4(r0, r1, r2, r3, addr) \
    asm volatile("ldmatrix.sync.aligned.m8n8.x4.shared.b16 {%0,%1,%2,%3}, [%4];" \
        : "=r"(r0), "=r"(r1), "=r"(r2), "=r"(r3) : "r"(addr))
#define LDSM4T(r0, r1, r2, r3, addr) \
    asm volatile("ldmatrix.sync.aligned.m8n8.x4.trans.shared.b16 {%0,%1,%2,%3}, [%4];" \
        : "=r"(r0), "=r"(r1), "=r"(r2), "=r"(r3) : "r"(addr))

__device__ __forceinline__ void mma_h(float c[4], const uint32_t a[4], const uint32_t b[2]) {
    asm volatile("mma.sync.aligned.m16n8k16.row.col.f32.f16.f16.f32 "
        "{%0,%1,%2,%3}, {%4,%5,%6,%7}, {%8,%9}, {%0,%1,%2,%3};"
        : "+f"(c[0]), "+f"(c[1]), "+f"(c[2]), "+f"(c[3])
        : "r"(a[0]), "r"(a[1]), "r"(a[2]), "r"(a[3]), "r"(b[0]), "r"(b[1]));
}

// ---------------------------------------------------------------------------
// fp16 GEMM: 128x128 tile, BK=64 halves, 2-stage pipeline.
// TRANSB=0: Bp [N,K] k-contig half -> smem [n][PAH], plain ldmatrix.
// TRANSB=1: Bp [K,N] n-contig -> smem [k][PBH], trans ldmatrix.
// AF32/BF32: operand is fp32 in gmem -> LDG + convert + STS (sync path);
//            otherwise cp.async direct half copy.
// ---------------------------------------------------------------------------
template<int TRANSB, int AF32, int BF32>
__device__ __forceinline__ void gemm_h(
    float acc[4][4][4],
    const void* __restrict__ Ap, int lda,
    const void* __restrict__ Bp, int ldb, int Ktot,
    __half* sA, __half* sB)
{
    const int BSTG = TRANSB ? BSTGH_T : BSTGH_N;
    int tid = threadIdx.x, lane = tid & 31, wid = tid >> 5;
    int wm = (wid & 1) * 64, wn = (wid >> 1) * 32;

    auto issue = [&](int t, int buf) {
        int k0 = t * BKH;
        if (AF32 == 0) {
            const __half* Ah = (const __half*)Ap;
            #pragma unroll
            for (int i = 0; i < 4; i++) {             // A: 128 rows x 64 halves
                int f = tid + i * 256;
                int row = f >> 3, seg = f & 7;
                CP16(sptr(sA + buf * ASTGH + row * PAH + seg * 8),
                     Ah + (size_t)row * lda + k0 + seg * 8);
            }
        } else {
            const float* Af = (const float*)Ap;
            #pragma unroll
            for (int i = 0; i < 4; i++) {             // A fp32 -> half
                int f = tid + i * 256;
                int row = f >> 3, seg = f & 7;
                const float* s = Af + (size_t)row * lda + k0 + seg * 8;
                float4 x0 = *(const float4*)s;
                float4 x1 = *(const float4*)(s + 4);
                uint4 y;
                __half2* hy = (__half2*)&y;
                hy[0] = __floats2half2_rn(x0.x, x0.y);
                hy[1] = __floats2half2_rn(x0.z, x0.w);
                hy[2] = __floats2half2_rn(x1.x, x1.y);
                hy[3] = __floats2half2_rn(x1.z, x1.w);
                *(uint4*)(sA + buf * ASTGH + row * PAH + seg * 8) = y;
            }
        }
        if (TRANSB == 1) {
            if (BF32 == 0) {
                const __half* Bh = (const __half*)Bp;
                #pragma unroll
                for (int i = 0; i < 4; i++) {         // B: 64 k x 128 n halves
                    int f = tid + i * 256;
                    int k = f >> 4, seg = f & 15;
                    CP16(sptr(sB + buf * BSTGH_T + k * PBH + seg * 8),
                         Bh + (size_t)(k0 + k) * ldb + seg * 8);
                }
            } else {
                const float* Bf = (const float*)Bp;
                #pragma unroll
                for (int i = 0; i < 8; i++) {         // B fp32 -> half
                    int f = tid + i * 256;
                    int k = f >> 5, seg = f & 31;
                    float4 v = *(const float4*)(Bf + (size_t)(k0 + k) * ldb + seg * 4);
                    __half2 h0 = __floats2half2_rn(v.x, v.y);
                    __half2 h1 = __floats2half2_rn(v.z, v.w);
                    *(__half2*)(sB + buf * BSTGH_T + k * PBH + seg * 4) = h0;
                    *(__half2*)(sB + buf * BSTGH_T + k * PBH + seg * 4 + 2) = h1;
                }
            }
        } else {
            const __half* Bh = (const __half*)Bp;
            #pragma unroll
            for (int i = 0; i < 4; i++) {             // B: 128 n x 64 k halves
                int f = tid + i * 256;
                int n = f >> 3, seg = f & 7;
                CP16(sptr(sB + buf * BSTGH_N + n * PAH + seg * 8),
                     Bh + (size_t)n * ldb + k0 + seg * 8);
            }
        }
        CP_COMMIT();
    };

    int T = Ktot / BKH;    // >= 2 for all callers
    issue(0, 0);
    for (int t = 0; t < T; t++) {
        if (t + 1 < T) { issue(t + 1, (t + 1) & 1); asm volatile("cp.async.wait_group 1;"); }
        else             asm volatile("cp.async.wait_group 0;");
        __syncthreads();
        uint32_t aB = sptr(sA + (t & 1) * ASTGH);
        uint32_t bB = sptr(sB + (t & 1) * BSTG);
        #pragma unroll
        for (int ks = 0; ks < 4; ks++) {
            int kh = ks * 16;
            uint32_t a[4][4];
            #pragma unroll
            for (int mf = 0; mf < 4; mf++) {
                uint32_t addr = aB +
                    ((wm + mf * 16 + (lane & 15)) * PAH + kh + ((lane >> 4) << 3)) * 2;
                LDSM4(a[mf][0], a[mf][1], a[mf][2], a[mf][3], addr);
            }
            uint32_t b[4][2];
            #pragma unroll
            for (int nfp = 0; nfp < 2; nfp++) {
                if (TRANSB == 0) {
                    uint32_t addr = bB +
                        ((wn + nfp * 16 + ((lane & 16) >> 1) + (lane & 7)) * PAH
                         + kh + (lane & 8)) * 2;
                    LDSM4(b[2 * nfp][0], b[2 * nfp][1],
                          b[2 * nfp + 1][0], b[2 * nfp + 1][1], addr);
                } else {
                    uint32_t addr = bB +
                        ((kh + (lane & 15)) * PBH + wn + nfp * 16 + ((lane & 16) >> 1)) * 2;
                    LDSM4T(b[2 * nfp][0], b[2 * nfp][1],
                           b[2 * nfp + 1][0], b[2 * nfp + 1][1], addr);
                }
            }
            #pragma unroll
            for (int mf = 0; mf < 4; mf++)
                #pragma unroll
                for (int nf = 0; nf < 4; nf++)
                    mma_h(acc[mf][nf], a[mf], b[nf]);
        }
        __syncthreads();
    }
}

// ---------------------------------------------------------------------------
// Kernel 1: projections -> half g_Q/g_K/g_V. Converts fp32 X and W on the fly.
// ---------------------------------------------------------------------------
__global__ __launch_bounds__(256, 2) void proj_tc(
    const float* __restrict__ Xk, const float* __restrict__ Xv, const float* __restrict__ Xq,
    const float* __restrict__ WK, const float* __restrict__ WV, const float* __restrict__ WQ)
{
    extern __shared__ __align__(16) __half fsh[];
    __half* sA = fsh;
    __half* sB = fsh + 2 * ASTGH;
    int z = blockIdx.z;
    int t = z / 3, h = z % 3;
    const float* X = (t == 0) ? Xk : (t == 1) ? Xv : Xq;
    const float* W = ((t == 0) ? WK : (t == 1) ? WV : WQ) + (size_t)h * E_ * D_;
    __half* Out    = (t == 0) ? g_K : (t == 1) ? g_V : g_Q;

    int m0 = blockIdx.y * 128, n0 = blockIdx.x * 128;
    float acc[4][4][4] = {};
    gemm_h<1, 1, 1>(acc, X + (size_t)m0 * E_, E_, W + n0, D_, E_, sA, sB);

    int lane = threadIdx.x & 31, wid = threadIdx.x >> 5;
    int wm = (wid & 1) * 64, wn = (wid >> 1) * 32;
    #pragma unroll
    for (int mf = 0; mf < 4; mf++) {
        #pragma unroll
        for (int half = 0; half < 2; half++) {
            int m = m0 + wm + mf * 16 + (lane >> 2) + half * 8;
            int bb = m >> 11, ss = m & (S_ - 1);
            __half* orow = Out + (((size_t)(bb * H_ + h)) * S_ + ss) * D_ + n0;
            #pragma unroll
            for (int nf = 0; nf < 4; nf++) {
                int col = wn + nf * 8 + 2 * (lane & 3);
                __half2 v = half ? __floats2half2_rn(acc[mf][nf][2], acc[mf][nf][3])
                                 : __floats2half2_rn(acc[mf][nf][0], acc[mf][nf][1]);
                *(__half2*)(orow + col) = v;
            }
        }
    }
}

// ---------------------------------------------------------------------------
// Kernel 2: scores + fused exp (fp16 MMA). Triangular grid.
// Writes UNNORMALIZED P = exp(s/sqrt(S)) (causally masked) to g_P and
// per-(row, 32-col stripe) partial sums to g_psum (quad-shfl reduced).
// ---------------------------------------------------------------------------
__global__ __launch_bounds__(256, 2) void scores_tc()
{
    int i = 135 - blockIdx.x;
    int qt = (int)((sqrtf(8.f * i + 1.f) - 1.f) * 0.5f);
    while ((qt + 1) * (qt + 2) / 2 <= i) qt++;
    while (qt * (qt + 1) / 2 > i) qt--;
    int kt = i - qt * (qt + 1) / 2;
    int bh = blockIdx.y;

    extern __shared__ __align__(16) __half fsh[];
    __half* sA = fsh;
    __half* sB = fsh + 2 * ASTGH;

    int q0 = qt * 128, k0 = kt * 128;
    const __half* Q = g_Q + (size_t)bh * S_ * D_ + (size_t)q0 * D_;
    const __half* K = g_K + (size_t)bh * S_ * D_ + (size_t)k0 * D_;
    float acc[4][4][4] = {};
    gemm_h<0, 0, 0>(acc, Q, D_, K, D_, D_, sA, sB);

    const float scale = 0.022097086912079612f;  // 1/sqrt(2048)
    int lane = threadIdx.x & 31, wid = threadIdx.x >> 5;
    int wm = (wid & 1) * 64, wn = (wid >> 1) * 32;
    int stripe = wid >> 1;                      // 0..3
    __half* Pb = g_P + (size_t)bh * S_ * S_;
    #pragma unroll
    for (int mf = 0; mf < 4; mf++) {
        #pragma unroll
        for (int half = 0; half < 2; half++) {
            int q = q0 + wm + mf * 16 + (lane >> 2) + half * 8;
            __half* orow = Pb + (size_t)q * S_ + k0;
            float rsum = 0.f;
            #pragma unroll
            for (int nf = 0; nf < 4; nf++) {
                int col = wn + nf * 8 + 2 * (lane & 3);
                int kg = k0 + col;
                float s0 = half ? acc[mf][nf][2] : acc[mf][nf][0];
                float s1 = half ? acc[mf][nf][3] : acc[mf][nf][1];
                float e0 = (kg     <= q) ? __expf(s0 * scale) : 0.f;
                float e1 = (kg + 1 <= q) ? __expf(s1 * scale) : 0.f;
                rsum += e0 + e1;
                *(__half2*)(orow + col) = __floats2half2_rn(e0, e1);
            }
            rsum += __shfl_xor_sync(~0u, rsum, 1);
            rsum += __shfl_xor_sync(~0u, rsum, 2);
            if ((lane & 3) == 0)
                g_psum[((size_t)bh * S_ + q) * 64 + kt * 4 + stripe] = rsum;
        }
    }
}

// ---------------------------------------------------------------------------
// Kernel 3: row-sum reduce -> g_rsum = 1/sum  (one WARP per row)
// ---------------------------------------------------------------------------
__global__ __launch_bounds__(256) void rowsum_kernel()
{
    int row = (blockIdx.x * 256 + threadIdx.x) >> 5;
    if (row >= NROWS) return;
    int lane = threadIdx.x & 31;
    int q = row & (S_ - 1);
    int nst = ((q >> 7) + 1) * 4;           // valid stripes (<= 64)
    const float* p = g_psum + (size_t)row * 64;
    float s = 0.f;
    for (int j = lane; j < nst; j += 32) s += p[j];
    #pragma unroll
    for (int o = 16; o; o >>= 1) s += __shfl_xor_sync(~0u, s, o);
    if (lane == 0) g_rsum[row] = 1.0f / s;
}

// ---------------------------------------------------------------------------
// Kernel 4: Z = P_unnorm @ V (fp16 MMA), normalized by g_rsum in epilogue
// ---------------------------------------------------------------------------
__global__ __launch_bounds__(256, 2) void pv_tc()
{
    int nt = blockIdx.x, qt = 15 - blockIdx.y, bh = blockIdx.z;
    extern __shared__ __align__(16) __half fsh[];
    __half* sA = fsh;
    __half* sB = fsh + 2 * ASTGH;

    int q0 = qt * 128, n0 = nt * 128;
    const __half* P = g_P + (size_t)bh * S_ * S_ + (size_t)q0 * S_;
    const __half* V = g_V + (size_t)bh * S_ * D_ + n0;
    float acc[4][4][4] = {};
    gemm_h<1, 0, 0>(acc, P, S_, V, D_, (qt + 1) * 128, sA, sB);

    int lane = threadIdx.x & 31, wid = threadIdx.x >> 5;
    int wm = (wid & 1) * 64, wn = (wid >> 1) * 32;
    int bb = bh / H_, h = bh - bb * H_;
    #pragma unroll
    for (int mf = 0; mf < 4; mf++) {
        #pragma unroll
        for (int half = 0; half < 2; half++) {
            int q = q0 + wm + mf * 16 + (lane >> 2) + half * 8;
            float inv = g_rsum[bh * S_ + q];
            __half* orow = g_C + ((size_t)(bb * S_ + q)) * E_ + h * D_ + n0;
            #pragma unroll
            for (int nf = 0; nf < 4; nf++) {
                int col = wn + nf * 8 + 2 * (lane & 3);
                __half2 v = half ? __floats2half2_rn(acc[mf][nf][2] * inv, acc[mf][nf][3] * inv)
                                 : __floats2half2_rn(acc[mf][nf][0] * inv, acc[mf][nf][1] * inv);
                *(__half2*)(orow + col) = v;
            }
        }
    }
}

// ---------------------------------------------------------------------------
// Kernel 5: Out = g_C @ Wo + bo (fp16 MMA, Wo fp32 converted on the fly)
// ---------------------------------------------------------------------------
__global__ __launch_bounds__(256, 2) void out_tc(
    const float* __restrict__ Wo, const float* __restrict__ bo, float* __restrict__ Out)
{
    extern __shared__ __align__(16) __half fsh[];
    __half* sA = fsh;
    __half* sB = fsh + 2 * ASTGH;
    int n0 = blockIdx.x * 128, m0 = blockIdx.y * 128;
    float acc[4][4][4] = {};
    gemm_h<1, 0, 1>(acc, g_C + (size_t)m0 * E_, E_, Wo + n0, E_, E_, sA, sB);

    int lane = threadIdx.x & 31, wid = threadIdx.x >> 5;
    int wm = (wid & 1) * 64, wn = (wid >> 1) * 32;
    #pragma unroll
    for (int mf = 0; mf < 4; mf++) {
        #pragma unroll
        for (int half = 0; half < 2; half++) {
            int m = m0 + wm + mf * 16 + (lane >> 2) + half * 8;
            float* orow = Out + (size_t)m * E_ + n0;
            #pragma unroll
            for (int nf = 0; nf < 4; nf++) {
                int col = wn + nf * 8 + 2 * (lane & 3);
                float2 bv = *(const float2*)(bo + n0 + col);
                float2 v = half ? make_float2(acc[mf][nf][2] + bv.x, acc[mf][nf][3] + bv.y)
                                : make_float2(acc[mf][nf][0] + bv.x, acc[mf][nf][1] + bv.y);
                *(float2*)(orow + col) = v;
            }
        }
    }
}

// ---------------------------------------------------------------------------
#define SMEM_HT ((2 * ASTGH + 2 * BSTGH_T) * 2)        // 71680 B
#define SMEM_HN ((2 * ASTGH + 2 * BSTGH_N) * 2)        // 73728 B

extern "C" void kernel_launch(void* const* d_in, const int* in_sizes, int n_in,
                              void* d_out, int out_size)
{
    const float* Xk = (const float*)d_in[0];
    const float* Xv = (const float*)d_in[1];
    const float* Xq = (const float*)d_in[2];
    const float* WK = (const float*)d_in[3];
    const float* WV = (const float*)d_in[4];
    const float* WQ = (const float*)d_in[5];
    const float* Wo = (const float*)d_in[6];
    const float* bo = (const float*)d_in[7];
    float* out = (float*)d_out;

    cudaFuncSetAttribute(proj_tc,   cudaFuncAttributeMaxDynamicSharedMemorySize, SMEM_HT);
    cudaFuncSetAttribute(scores_tc, cudaFuncAttributeMaxDynamicSharedMemorySize, SMEM_HN);
    cudaFuncSetAttribute(pv_tc,     cudaFuncAttributeMaxDynamicSharedMemorySize, SMEM_HT);
    cudaFuncSetAttribute(out_tc,    cudaFuncAttributeMaxDynamicSharedMemorySize, SMEM_HT);

    proj_tc<<<dim3(2, 64, 9), 256, SMEM_HT>>>(Xk, Xv, Xq, WK, WV, WQ);
    scores_tc<<<dim3(136, 12), 256, SMEM_HN>>>();
    rowsum_kernel<<<dim3((NROWS * 32 + 255) / 256), 256>>>();
    pv_tc<<<dim3(2, 16, 12), 256, SMEM_HT>>>();
    out_tc<<<dim3(6, 64), 256, SMEM_HT>>>(Wo, bo, out);
}

// round 16
// speedup vs baseline: 1.1267x; 1.1267x over previous
#include <cuda_runtime.h>
#include <cuda_fp16.h>
#include <cstdint>
#include <math.h>

#define B_  4
#define S_  2048
#define E_  768
#define H_  3
#define D_  256

// fp16 GEMM params
#define BKH 64
#define PAH 72      // halves; ldmatrix group banks all distinct
#define PBH 136     // halves; ldmatrix.trans group banks all distinct
#define ASTGH (128 * PAH)
#define BSTGH_T (BKH * PBH)
#define BSTGH_N (128 * PAH)

#define NX ((size_t)B_ * S_ * E_)   // 6291456
#define NW ((size_t)H_ * E_ * D_)   // 589824
#define NROWS (B_ * H_ * S_)        // 24576
#define NX4 (NX / 4)
#define NW4 (NW / 4)
#define NWO4 ((size_t)E_ * E_ / 4)
#define CVT_TOTAL4 (3 * NX4 + 3 * NW4 + NWO4)   // 5308416

// Scratch (device globals — no allocation allowed)
__device__ __half g_Xh[3 * NX];                     // Xk, Xv, Xq (half)
__device__ __half g_Wh[3 * NW];                     // WK, WV, WQ (half)
__device__ __half g_Woh[(size_t)E_ * E_];           // Wo (half)
__device__ __half g_Q[(size_t)B_ * H_ * S_ * D_];
__device__ __half g_K[(size_t)B_ * H_ * S_ * D_];
__device__ __half g_V[(size_t)B_ * H_ * S_ * D_];
__device__ __half g_P[(size_t)B_ * H_ * S_ * S_];   // UNNORMALIZED exp scores (half)
__device__ float  g_psum[(size_t)NROWS * 64];       // per-(row, stripe) partial sums
__device__ float  g_rsum[NROWS];                    // 1 / row sum
__device__ __half g_C[(size_t)B_ * S_ * E_];        // concat heads (half)

// ---------------------------------------------------------------------------
__device__ __forceinline__ uint32_t sptr(const void* p) {
    return (uint32_t)__cvta_generic_to_shared(p);
}
#define CP16(dst, src) \
    asm volatile("cp.async.cg.shared.global [%0], [%1], 16;" :: "r"(dst), "l"(src))
#define CP_COMMIT() asm volatile("cp.async.commit_group;")
#define LDSM4(r0, r1, r2, r3, addr) \
    asm volatile("ldmatrix.sync.aligned.m8n8.x4.shared.b16 {%0,%1,%2,%3}, [%4];" \
        : "=r"(r0), "=r"(r1), "=r"(r2), "=r"(r3) : "r"(addr))
#define LDSM4T(r0, r1, r2, r3, addr) \
    asm volatile("ldmatrix.sync.aligned.m8n8.x4.trans.shared.b16 {%0,%1,%2,%3}, [%4];" \
        : "=r"(r0), "=r"(r1), "=r"(r2), "=r"(r3) : "r"(addr))

__device__ __forceinline__ void mma_h(float c[4], const uint32_t a[4], const uint32_t b[2]) {
    asm volatile("mma.sync.aligned.m16n8k16.row.col.f32.f16.f16.f32 "
        "{%0,%1,%2,%3}, {%4,%5,%6,%7}, {%8,%9}, {%0,%1,%2,%3};"
        : "+f"(c[0]), "+f"(c[1]), "+f"(c[2]), "+f"(c[3])
        : "r"(a[0]), "r"(a[1]), "r"(a[2]), "r"(a[3]), "r"(b[0]), "r"(b[1]));
}

// ---------------------------------------------------------------------------
// fp16 GEMM: 128x128 tile, BK=64 halves, 2-stage cp.async.
// TRANSB=0: Bp [N,K] k-contig -> smem [n][PAH], plain ldmatrix.
// TRANSB=1: Bp [K,N] n-contig -> smem [k][PBH], trans ldmatrix.
// ---------------------------------------------------------------------------
template<int TRANSB>
__device__ __forceinline__ void gemm_h(
    float acc[4][4][4],
    const __half* __restrict__ A, int lda,
    const __half* __restrict__ Bp, int ldb, int Ktot,
    __half* sA, __half* sB)
{
    const int BSTG = TRANSB ? BSTGH_T : BSTGH_N;
    int tid = threadIdx.x, lane = tid & 31, wid = tid >> 5;
    int wm = (wid & 1) * 64, wn = (wid >> 1) * 32;

    auto issue = [&](int t, int buf) {
        int k0 = t * BKH;
        #pragma unroll
        for (int i = 0; i < 4; i++) {                 // A: 128 rows x 64 halves
            int f = tid + i * 256;
            int row = f >> 3, seg = f & 7;
            CP16(sptr(sA + buf * ASTGH + row * PAH + seg * 8),
                 A + (size_t)row * lda + k0 + seg * 8);
        }
        if (TRANSB == 1) {
            #pragma unroll
            for (int i = 0; i < 4; i++) {             // B: 64 k x 128 n halves
                int f = tid + i * 256;
                int k = f >> 4, seg = f & 15;
                CP16(sptr(sB + buf * BSTGH_T + k * PBH + seg * 8),
                     Bp + (size_t)(k0 + k) * ldb + seg * 8);
            }
        } else {
            #pragma unroll
            for (int i = 0; i < 4; i++) {             // B: 128 n x 64 k halves
                int f = tid + i * 256;
                int n = f >> 3, seg = f & 7;
                CP16(sptr(sB + buf * BSTGH_N + n * PAH + seg * 8),
                     Bp + (size_t)n * ldb + k0 + seg * 8);
            }
        }
        CP_COMMIT();
    };

    int T = Ktot / BKH;    // >= 2 for all callers
    issue(0, 0);
    for (int t = 0; t < T; t++) {
        if (t + 1 < T) { issue(t + 1, (t + 1) & 1); asm volatile("cp.async.wait_group 1;"); }
        else             asm volatile("cp.async.wait_group 0;");
        __syncthreads();
        uint32_t aB = sptr(sA + (t & 1) * ASTGH);
        uint32_t bB = sptr(sB + (t & 1) * BSTG);
        #pragma unroll
        for (int ks = 0; ks < 4; ks++) {
            int kh = ks * 16;
            uint32_t a[4][4];
            #pragma unroll
            for (int mf = 0; mf < 4; mf++) {
                uint32_t addr = aB +
                    ((wm + mf * 16 + (lane & 15)) * PAH + kh + ((lane >> 4) << 3)) * 2;
                LDSM4(a[mf][0], a[mf][1], a[mf][2], a[mf][3], addr);
            }
            uint32_t b[4][2];
            #pragma unroll
            for (int nfp = 0; nfp < 2; nfp++) {
                if (TRANSB == 0) {
                    uint32_t addr = bB +
                        ((wn + nfp * 16 + ((lane & 16) >> 1) + (lane & 7)) * PAH
                         + kh + (lane & 8)) * 2;
                    LDSM4(b[2 * nfp][0], b[2 * nfp][1],
                          b[2 * nfp + 1][0], b[2 * nfp + 1][1], addr);
                } else {
                    uint32_t addr = bB +
                        ((kh + (lane & 15)) * PBH + wn + nfp * 16 + ((lane & 16) >> 1)) * 2;
                    LDSM4T(b[2 * nfp][0], b[2 * nfp][1],
                           b[2 * nfp + 1][0], b[2 * nfp + 1][1], addr);
                }
            }
            #pragma unroll
            for (int mf = 0; mf < 4; mf++)
                #pragma unroll
                for (int nf = 0; nf < 4; nf++)
                    mma_h(acc[mf][nf], a[mf], b[nf]);
        }
        __syncthreads();
    }
}

// ---------------------------------------------------------------------------
// Kernel 0: fp32 -> fp16 conversion, flat 1D grid (no wasted blocks)
// ---------------------------------------------------------------------------
__global__ __launch_bounds__(256) void convert_all(
    const float* __restrict__ Xk, const float* __restrict__ Xv, const float* __restrict__ Xq,
    const float* __restrict__ WK, const float* __restrict__ WV, const float* __restrict__ WQ,
    const float* __restrict__ Wo)
{
    size_t i = (size_t)blockIdx.x * 256 + threadIdx.x;
    if (i >= CVT_TOTAL4) return;
    const float* src; __half* dst; size_t off;
    if      (i <     NX4) { src = Xk; dst = g_Xh;          off = i; }
    else if (i < 2 * NX4) { src = Xv; dst = g_Xh + NX;     off = i - NX4; }
    else if (i < 3 * NX4) { src = Xq; dst = g_Xh + 2 * NX; off = i - 2 * NX4; }
    else if (i < 3 * NX4 + NW4)     { src = WK; dst = g_Wh;          off = i - 3 * NX4; }
    else if (i < 3 * NX4 + 2 * NW4) { src = WV; dst = g_Wh + NW;     off = i - 3 * NX4 - NW4; }
    else if (i < 3 * NX4 + 3 * NW4) { src = WQ; dst = g_Wh + 2 * NW; off = i - 3 * NX4 - 2 * NW4; }
    else                            { src = Wo; dst = g_Woh;         off = i - 3 * NX4 - 3 * NW4; }
    float4 x = ((const float4*)src)[off];
    __half2* d2 = (__half2*)dst;
    d2[off * 2]     = __floats2half2_rn(x.x, x.y);
    d2[off * 2 + 1] = __floats2half2_rn(x.z, x.w);
}

// ---------------------------------------------------------------------------
// Kernel 1: projections (fp16) -> half outputs g_Q/g_K/g_V
// ---------------------------------------------------------------------------
__global__ __launch_bounds__(256, 2) void proj_tc()
{
    extern __shared__ __align__(16) __half fsh[];
    __half* sA = fsh;
    __half* sB = fsh + 2 * ASTGH;
    int z = blockIdx.z;
    int t = z / 3, h = z % 3;
    const __half* X = g_Xh + (size_t)t * NX;
    const __half* W = g_Wh + (size_t)t * NW + (size_t)h * E_ * D_;
    __half* Out     = (t == 0) ? g_K : (t == 1) ? g_V : g_Q;

    int m0 = blockIdx.y * 128, n0 = blockIdx.x * 128;
    float acc[4][4][4] = {};
    gemm_h<1>(acc, X + (size_t)m0 * E_, E_, W + n0, D_, E_, sA, sB);

    int lane = threadIdx.x & 31, wid = threadIdx.x >> 5;
    int wm = (wid & 1) * 64, wn = (wid >> 1) * 32;
    #pragma unroll
    for (int mf = 0; mf < 4; mf++) {
        #pragma unroll
        for (int half = 0; half < 2; half++) {
            int m = m0 + wm + mf * 16 + (lane >> 2) + half * 8;
            int bb = m >> 11, ss = m & (S_ - 1);
            __half* orow = Out + (((size_t)(bb * H_ + h)) * S_ + ss) * D_ + n0;
            #pragma unroll
            for (int nf = 0; nf < 4; nf++) {
                int col = wn + nf * 8 + 2 * (lane & 3);
                __half2 v = half ? __floats2half2_rn(acc[mf][nf][2], acc[mf][nf][3])
                                 : __floats2half2_rn(acc[mf][nf][0], acc[mf][nf][1]);
                *(__half2*)(orow + col) = v;
            }
        }
    }
}

// ---------------------------------------------------------------------------
// Kernel 2: scores + fused exp (fp16 MMA). Triangular grid.
// Writes UNNORMALIZED P = exp(s/sqrt(S)) (causally masked) to g_P and
// per-(row, 32-col stripe) partial sums to g_psum (quad-shfl reduced).
// ---------------------------------------------------------------------------
__global__ __launch_bounds__(256, 2) void scores_tc()
{
    int i = 135 - blockIdx.x;
    int qt = (int)((sqrtf(8.f * i + 1.f) - 1.f) * 0.5f);
    while ((qt + 1) * (qt + 2) / 2 <= i) qt++;
    while (qt * (qt + 1) / 2 > i) qt--;
    int kt = i - qt * (qt + 1) / 2;
    int bh = blockIdx.y;

    extern __shared__ __align__(16) __half fsh[];
    __half* sA = fsh;
    __half* sB = fsh + 2 * ASTGH;

    int q0 = qt * 128, k0 = kt * 128;
    const __half* Q = g_Q + (size_t)bh * S_ * D_ + (size_t)q0 * D_;
    const __half* K = g_K + (size_t)bh * S_ * D_ + (size_t)k0 * D_;
    float acc[4][4][4] = {};
    gemm_h<0>(acc, Q, D_, K, D_, D_, sA, sB);

    const float scale = 0.022097086912079612f;  // 1/sqrt(2048)
    int lane = threadIdx.x & 31, wid = threadIdx.x >> 5;
    int wm = (wid & 1) * 64, wn = (wid >> 1) * 32;
    int stripe = wid >> 1;                      // 0..3
    __half* Pb = g_P + (size_t)bh * S_ * S_;
    #pragma unroll
    for (int mf = 0; mf < 4; mf++) {
        #pragma unroll
        for (int half = 0; half < 2; half++) {
            int q = q0 + wm + mf * 16 + (lane >> 2) + half * 8;
            __half* orow = Pb + (size_t)q * S_ + k0;
            float rsum = 0.f;
            #pragma unroll
            for (int nf = 0; nf < 4; nf++) {
                int col = wn + nf * 8 + 2 * (lane & 3);
                int kg = k0 + col;
                float s0 = half ? acc[mf][nf][2] : acc[mf][nf][0];
                float s1 = half ? acc[mf][nf][3] : acc[mf][nf][1];
                float e0 = (kg     <= q) ? __expf(s0 * scale) : 0.f;
                float e1 = (kg + 1 <= q) ? __expf(s1 * scale) : 0.f;
                rsum += e0 + e1;
                *(__half2*)(orow + col) = __floats2half2_rn(e0, e1);
            }
            rsum += __shfl_xor_sync(~0u, rsum, 1);
            rsum += __shfl_xor_sync(~0u, rsum, 2);
            if ((lane & 3) == 0)
                g_psum[((size_t)bh * S_ + q) * 64 + kt * 4 + stripe] = rsum;
        }
    }
}

// ---------------------------------------------------------------------------
// Kernel 3: row-sum reduce -> g_rsum = 1/sum  (one WARP per row)
// ---------------------------------------------------------------------------
__global__ __launch_bounds__(256) void rowsum_kernel()
{
    int row = (blockIdx.x * 256 + threadIdx.x) >> 5;
    if (row >= NROWS) return;
    int lane = threadIdx.x & 31;
    int q = row & (S_ - 1);
    int nst = ((q >> 7) + 1) * 4;           // valid stripes (<= 64)
    const float* p = g_psum + (size_t)row * 64;
    float s = 0.f;
    for (int j = lane; j < nst; j += 32) s += p[j];
    #pragma unroll
    for (int o = 16; o; o >>= 1) s += __shfl_xor_sync(~0u, s, o);
    if (lane == 0) g_rsum[row] = 1.0f / s;
}

// ---------------------------------------------------------------------------
// Kernel 4: Z = P_unnorm @ V (fp16 MMA), normalized by g_rsum in epilogue
// ---------------------------------------------------------------------------
__global__ __launch_bounds__(256, 2) void pv_tc()
{
    int nt = blockIdx.x, qt = 15 - blockIdx.y, bh = blockIdx.z;
    extern __shared__ __align__(16) __half fsh[];
    __half* sA = fsh;
    __half* sB = fsh + 2 * ASTGH;

    int q0 = qt * 128, n0 = nt * 128;
    const __half* P = g_P + (size_t)bh * S_ * S_ + (size_t)q0 * S_;
    const __half* V = g_V + (size_t)bh * S_ * D_ + n0;
    float acc[4][4][4] = {};
    gemm_h<1>(acc, P, S_, V, D_, (qt + 1) * 128, sA, sB);

    int lane = threadIdx.x & 31, wid = threadIdx.x >> 5;
    int wm = (wid & 1) * 64, wn = (wid >> 1) * 32;
    int bb = bh / H_, h = bh - bb * H_;
    #pragma unroll
    for (int mf = 0; mf < 4; mf++) {
        #pragma unroll
        for (int half = 0; half < 2; half++) {
            int q = q0 + wm + mf * 16 + (lane >> 2) + half * 8;
            float inv = g_rsum[bh * S_ + q];
            __half* orow = g_C + ((size_t)(bb * S_ + q)) * E_ + h * D_ + n0;
            #pragma unroll
            for (int nf = 0; nf < 4; nf++) {
                int col = wn + nf * 8 + 2 * (lane & 3);
                __half2 v = half ? __floats2half2_rn(acc[mf][nf][2] * inv, acc[mf][nf][3] * inv)
                                 : __floats2half2_rn(acc[mf][nf][0] * inv, acc[mf][nf][1] * inv);
                *(__half2*)(orow + col) = v;
            }
        }
    }
}

// ---------------------------------------------------------------------------
// Kernel 5: Out = g_C @ Wo + bo (fp16 MMA, pre-converted Wo)
// ---------------------------------------------------------------------------
__global__ __launch_bounds__(256, 2) void out_tc(
    const float* __restrict__ bo, float* __restrict__ Out)
{
    extern __shared__ __align__(16) __half fsh[];
    __half* sA = fsh;
    __half* sB = fsh + 2 * ASTGH;
    int n0 = blockIdx.x * 128, m0 = blockIdx.y * 128;
    float acc[4][4][4] = {};
    gemm_h<1>(acc, g_C + (size_t)m0 * E_, E_, g_Woh + n0, E_, E_, sA, sB);

    int lane = threadIdx.x & 31, wid = threadIdx.x >> 5;
    int wm = (wid & 1) * 64, wn = (wid >> 1) * 32;
    #pragma unroll
    for (int mf = 0; mf < 4; mf++) {
        #pragma unroll
        for (int half = 0; half < 2; half++) {
            int m = m0 + wm + mf * 16 + (lane >> 2) + half * 8;
            float* orow = Out + (size_t)m * E_ + n0;
            #pragma unroll
            for (int nf = 0; nf < 4; nf++) {
                int col = wn + nf * 8 + 2 * (lane & 3);
                float2 bv = *(const float2*)(bo + n0 + col);
                float2 v = half ? make_float2(acc[mf][nf][2] + bv.x, acc[mf][nf][3] + bv.y)
                                : make_float2(acc[mf][nf][0] + bv.x, acc[mf][nf][1] + bv.y);
                *(float2*)(orow + col) = v;
            }
        }
    }
}

// ---------------------------------------------------------------------------
#define SMEM_HT ((2 * ASTGH + 2 * BSTGH_T) * 2)        // 71680 B
#define SMEM_HN ((2 * ASTGH + 2 * BSTGH_N) * 2)        // 73728 B

extern "C" void kernel_launch(void* const* d_in, const int* in_sizes, int n_in,
                              void* d_out, int out_size)
{
    const float* Xk = (const float*)d_in[0];
    const float* Xv = (const float*)d_in[1];
    const float* Xq = (const float*)d_in[2];
    const float* WK = (const float*)d_in[3];
    const float* WV = (const float*)d_in[4];
    const float* WQ = (const float*)d_in[5];
    const float* Wo = (const float*)d_in[6];
    const float* bo = (const float*)d_in[7];
    float* out = (float*)d_out;

    cudaFuncSetAttribute(proj_tc,   cudaFuncAttributeMaxDynamicSharedMemorySize, SMEM_HT);
    cudaFuncSetAttribute(scores_tc, cudaFuncAttributeMaxDynamicSharedMemorySize, SMEM_HN);
    cudaFuncSetAttribute(pv_tc,     cudaFuncAttributeMaxDynamicSharedMemorySize, SMEM_HT);
    cudaFuncSetAttribute(out_tc,    cudaFuncAttributeMaxDynamicSharedMemorySize, SMEM_HT);

    convert_all<<<dim3((unsigned)((CVT_TOTAL4 + 255) / 256)), 256>>>(Xk, Xv, Xq, WK, WV, WQ, Wo);
    proj_tc<<<dim3(2, 64, 9), 256, SMEM_HT>>>();
    scores_tc<<<dim3(136, 12), 256, SMEM_HN>>>();
    rowsum_kernel<<<dim3((NROWS * 32 + 255) / 256), 256>>>();
    pv_tc<<<dim3(2, 16, 12), 256, SMEM_HT>>>();
    out_tc<<<dim3(6, 64), 256, SMEM_HT>>>(bo, out);
}